// round 10
// baseline (speedup 1.0000x reference)
#include <cuda_runtime.h>

#define M_PILLARS 16384
#define N_POINTS  4096
#define C_FEAT    64
#define RADIUS2   1.0f
#define VX        0.16f
#define VY        0.16f
#define PCY      -25.6f

#define GW        52            // grid cells per dim (cell size = 1.0 = R)
#define NCELLS    (GW * GW)     // 2704
#define SENT      0x7fffffffu

__device__ int    g_bin_start[NCELLS + 1];
__device__ float4 g_sorted[N_POINTS];    // x, y, idx(bits), pad

__device__ __forceinline__ int cell_of(float x, float y) {
    int gx = (int)floorf(x);            // cell size 1.0, x in [0, 51.2)
    int gy = (int)floorf(y + 25.6f);    // y in [-25.6, 25.6)
    gx = min(max(gx, 0), GW - 1);
    gy = min(max(gy, 0), GW - 1);
    return gy * GW + gx;
}

// ── Single-block prep: count + 3-level scan + scatter ───────────────────
__global__ __launch_bounds__(1024)
void k_prep(const float* __restrict__ seg_points) {
    __shared__ int cnt[NCELLS];
    __shared__ int cur[NCELLS];
    __shared__ int wsum[32];

    const int t    = threadIdx.x;
    const int lane = t & 31;
    const int w    = t >> 5;

    for (int i = t; i < NCELLS; i += 1024) cnt[i] = 0;
    __syncthreads();

    // Vectorized point load: 3 float4 = 12 floats = points 4t..4t+3
    const float4* sp4 = (const float4*)seg_points;
    const float4 a = sp4[3 * t + 0];
    const float4 b = sp4[3 * t + 1];
    const float4 c = sp4[3 * t + 2];

    float xk[4], yk[4];
    int   ck[4];
    xk[0] = a.x; yk[0] = a.y;
    xk[1] = a.w; yk[1] = b.x;
    xk[2] = b.z; yk[2] = b.w;
    xk[3] = c.y; yk[3] = c.z;
    #pragma unroll
    for (int k = 0; k < 4; k++) {
        ck[k] = cell_of(xk[k], yk[k]);
        atomicAdd(&cnt[ck[k]], 1);
    }
    __syncthreads();

    // 3-level exclusive scan: 3 cells per thread
    const int base = t * 3;
    int v0 = (base + 0 < NCELLS) ? cnt[base + 0] : 0;
    int v1 = (base + 1 < NCELLS) ? cnt[base + 1] : 0;
    int v2 = (base + 2 < NCELLS) ? cnt[base + 2] : 0;
    int s  = v0 + v1 + v2;

    int incl = s;
    #pragma unroll
    for (int d = 1; d < 32; d <<= 1) {
        int up = __shfl_up_sync(0xffffffffu, incl, d);
        if (lane >= d) incl += up;
    }
    if (lane == 31) wsum[w] = incl;
    __syncthreads();
    if (w == 0) {
        int ws = wsum[lane];
        int wi = ws;
        #pragma unroll
        for (int d = 1; d < 32; d <<= 1) {
            int up = __shfl_up_sync(0xffffffffu, wi, d);
            if (lane >= d) wi += up;
        }
        wsum[lane] = wi - ws;
    }
    __syncthreads();

    const int excl = incl - s + wsum[w];
    if (base + 0 < NCELLS) { g_bin_start[base + 0] = excl;           cur[base + 0] = excl; }
    if (base + 1 < NCELLS) { g_bin_start[base + 1] = excl + v0;      cur[base + 1] = excl + v0; }
    if (base + 2 < NCELLS) { g_bin_start[base + 2] = excl + v0 + v1; cur[base + 2] = excl + v0 + v1; }
    if (t == 0) g_bin_start[NCELLS] = N_POINTS;
    __syncthreads();

    #pragma unroll
    for (int k = 0; k < 4; k++) {
        const int pos = atomicAdd(&cur[ck[k]], 1);
        g_sorted[pos] = make_float4(xk[k], yk[k], __int_as_float(4 * t + k), 0.0f);
    }
}

// ── Query (16 lanes per pillar) + fuse (warp per 2 pillars) ─────────────
// 256 threads/block → 16 pillars/block → grid 1024
__global__ __launch_bounds__(256)
void k_query_fuse(const float* __restrict__ pillar_feature,
                  const int*   __restrict__ coors,
                  const float* __restrict__ seg_feats,
                  float*       __restrict__ out) {
    __shared__ int4 sidx[16];

    const int t    = threadIdx.x;
    const int warp = t >> 5;
    const int lane = t & 31;
    const int sub  = lane & 15;           // lane within group of 16
    const int pl   = t >> 4;              // pillar within block (0..15)
    const int m    = blockIdx.x * 16 + pl;

    // ── Phase A: 16-lane ball query ──
    {
        const float px = ((float)__ldg(&coors[m * 4 + 3]) + 0.5f) * VX;
        const float py = ((float)__ldg(&coors[m * 4 + 2]) + 0.5f) * VY + PCY;

        const int cx = min(max((int)floorf(px), 0), GW - 1);
        const int cy = min(max((int)floorf(py + 25.6f), 0), GW - 1);
        const int cx0 = max(cx - 1, 0), cx1 = min(cx + 1, GW - 1);
        const int cy0 = max(cy - 1, 0), cy1 = min(cy + 1, GW - 1);
        const int cyn = cy1 - cy0;        // 1 or 2 extra rows

        // Hoist all row ranges: 6 independent loads (MLP)
        int s0, e0, s1, e1, s2, e2;
        s0 = __ldg(&g_bin_start[cy0 * GW + cx0]);
        e0 = __ldg(&g_bin_start[cy0 * GW + cx1 + 1]);
        {
            const int gy1 = min(cy0 + 1, cy1);
            s1 = __ldg(&g_bin_start[gy1 * GW + cx0]);
            e1 = __ldg(&g_bin_start[gy1 * GW + cx1 + 1]);
            const int gy2 = cy1;
            s2 = __ldg(&g_bin_start[gy2 * GW + cx0]);
            e2 = __ldg(&g_bin_start[gy2 * GW + cx1 + 1]);
        }
        if (cyn < 1) { s1 = 0; e1 = 0; }
        if (cyn < 2) { s2 = 0; e2 = 0; }

        // per-lane 4 smallest in-radius indices (sorted ascending)
        unsigned c0 = SENT, c1 = SENT, c2 = SENT, c3 = SENT;

        #define SCAN_ROW(S, E)                                               \
            for (int j = (S) + sub; j < (E); j += 16) {                      \
                float4 p = g_sorted[j];                                      \
                float dx = px - p.x;                                         \
                float dy = py - p.y;                                         \
                if (dx * dx + dy * dy < RADIUS2) {                           \
                    unsigned v = (unsigned)__float_as_int(p.z);              \
                    if (v < c3) {                                            \
                        c3 = v;                                              \
                        unsigned tmp;                                        \
                        if (c3 < c2) { tmp = c2; c2 = c3; c3 = tmp; }        \
                        if (c2 < c1) { tmp = c1; c1 = c2; c2 = tmp; }        \
                        if (c1 < c0) { tmp = c0; c0 = c1; c1 = tmp; }        \
                    }                                                        \
                }                                                            \
            }
        SCAN_ROW(s0, e0)
        SCAN_ROW(s1, e1)
        SCAN_ROW(s2, e2)
        #undef SCAN_ROW

        // 16-lane merge via REDUX: ALWAYS 4 rounds, no divergent exit.
        const unsigned gmask = 0xFFFFu << (lane & 16);
        unsigned res0, res1, res2, res3;
        {
            unsigned mn;
            #define QMIN(dst)                                                \
                mn = __reduce_min_sync(gmask, c0);                           \
                dst = mn;                                                    \
                if (c0 == mn && mn != SENT) { c0 = c1; c1 = c2; c2 = c3; c3 = SENT; }
            QMIN(res0)
            QMIN(res1)
            QMIN(res2)
            QMIN(res3)
            #undef QMIN
        }

        int i0, i1, i2, i3;
        if (res0 == SENT) { i0 = i1 = i2 = i3 = 0; }
        else {
            i0 = (int)res0;
            i1 = (res1 == SENT) ? i0 : (int)res1;
            i2 = (res2 == SENT) ? i0 : (int)res2;
            i3 = (res3 == SENT) ? i0 : (int)res3;
        }
        if (sub == 0) sidx[pl] = make_int4(i0, i1, i2, i3);
    }
    __syncthreads();

    // ── Phase B: warp-per-pillar coalesced fuse (2 pillars per warp) ──
    const int pbase = blockIdx.x * 16 + warp * 2;

    #pragma unroll
    for (int k = 0; k < 2; k++) {
        const int p = pbase + k;
        const int4 id = sidx[warp * 2 + k];

        const size_t mrow = (size_t)p * C_FEAT;
        float v0 = pillar_feature[mrow + lane];
        float v1 = pillar_feature[mrow + lane + 32];

        // Reference quirk: flag = (sum of indices) > 0
        if (id.x + id.y + id.z + id.w > 0) {
            const size_t r0 = (size_t)id.x * C_FEAT;
            const size_t r1 = (size_t)id.y * C_FEAT;
            const size_t r2 = (size_t)id.z * C_FEAT;
            const size_t r3 = (size_t)id.w * C_FEAT;

            float a0 = seg_feats[r0 + lane];
            float a1 = seg_feats[r1 + lane];
            float a2 = seg_feats[r2 + lane];
            float a3 = seg_feats[r3 + lane];
            float b0 = seg_feats[r0 + lane + 32];
            float b1 = seg_feats[r1 + lane + 32];
            float b2 = seg_feats[r2 + lane + 32];
            float b3 = seg_feats[r3 + lane + 32];

            v0 += fmaxf(fmaxf(a0, a1), fmaxf(a2, a3));
            v1 += fmaxf(fmaxf(b0, b1), fmaxf(b2, b3));
        }

        out[mrow + lane]      = v0;
        out[mrow + lane + 32] = v1;
    }
}

extern "C" void kernel_launch(void* const* d_in, const int* in_sizes, int n_in,
                              void* d_out, int out_size) {
    const float* pillar_feature = (const float*)d_in[0];  // [M, 64]
    const int*   coors          = (const int*)  d_in[1];  // [M, 4]
    const float* seg_feats      = (const float*)d_in[2];  // [N, 64]
    const float* seg_points     = (const float*)d_in[3];  // [N, 3]
    float* out = (float*)d_out;                            // [M, 64]

    k_prep<<<1, 1024>>>(seg_points);
    k_query_fuse<<<M_PILLARS / 16, 256>>>(pillar_feature, coors, seg_feats, out);
}

// round 11
// speedup vs baseline: 1.0626x; 1.0626x over previous
#include <cuda_runtime.h>

#define M_PILLARS 16384
#define N_POINTS  4096
#define C_FEAT    64
#define RADIUS2   1.0f
#define VX        0.16f
#define VY        0.16f
#define PCY      -25.6f

#define GW        52            // grid cells per dim (cell size = 1.0 = R)
#define NCELLS    (GW * GW)     // 2704
#define SENT      0x7fffffffu

__device__ int    g_bin_start[NCELLS + 1];
__device__ int    g_cursor[NCELLS];
__device__ float4 g_sorted[N_POINTS];    // x, y, idx(bits), pad

__device__ __forceinline__ int cell_of(float x, float y) {
    int gx = (int)floorf(x);            // cell size 1.0, x in [0, 51.2)
    int gy = (int)floorf(y + 25.6f);    // y in [-25.6, 25.6)
    gx = min(max(gx, 0), GW - 1);
    gy = min(max(gy, 0), GW - 1);
    return gy * GW + gx;
}

// ── Kernel 1: count + scan (single block) ────────────────────────────────
__global__ __launch_bounds__(1024)
void k_count_scan(const float* __restrict__ seg_points) {
    __shared__ int cnt[NCELLS];
    __shared__ int wsum[32];

    const int t    = threadIdx.x;
    const int lane = t & 31;
    const int w    = t >> 5;

    for (int i = t; i < NCELLS; i += 1024) cnt[i] = 0;
    __syncthreads();

    // Vectorized point load: 3 float4 = 12 floats = points 4t..4t+3
    const float4* sp4 = (const float4*)seg_points;
    const float4 a = sp4[3 * t + 0];
    const float4 b = sp4[3 * t + 1];
    const float4 c = sp4[3 * t + 2];

    atomicAdd(&cnt[cell_of(a.x, a.y)], 1);
    atomicAdd(&cnt[cell_of(a.w, b.x)], 1);
    atomicAdd(&cnt[cell_of(b.z, b.w)], 1);
    atomicAdd(&cnt[cell_of(c.y, c.z)], 1);
    __syncthreads();

    // 3-level exclusive scan: 3 cells per thread
    const int base = t * 3;
    int v0 = (base + 0 < NCELLS) ? cnt[base + 0] : 0;
    int v1 = (base + 1 < NCELLS) ? cnt[base + 1] : 0;
    int v2 = (base + 2 < NCELLS) ? cnt[base + 2] : 0;
    int s  = v0 + v1 + v2;

    int incl = s;
    #pragma unroll
    for (int d = 1; d < 32; d <<= 1) {
        int up = __shfl_up_sync(0xffffffffu, incl, d);
        if (lane >= d) incl += up;
    }
    if (lane == 31) wsum[w] = incl;
    __syncthreads();
    if (w == 0) {
        int ws = wsum[lane];
        int wi = ws;
        #pragma unroll
        for (int d = 1; d < 32; d <<= 1) {
            int up = __shfl_up_sync(0xffffffffu, wi, d);
            if (lane >= d) wi += up;
        }
        wsum[lane] = wi - ws;
    }
    __syncthreads();

    const int excl = incl - s + wsum[w];
    if (base + 0 < NCELLS) { g_bin_start[base + 0] = excl;           g_cursor[base + 0] = excl; }
    if (base + 1 < NCELLS) { g_bin_start[base + 1] = excl + v0;      g_cursor[base + 1] = excl + v0; }
    if (base + 2 < NCELLS) { g_bin_start[base + 2] = excl + v0 + v1; g_cursor[base + 2] = excl + v0 + v1; }
    if (t == 0) g_bin_start[NCELLS] = N_POINTS;
}

// ── Kernel 2: parallel scatter (16 blocks × 256) ─────────────────────────
__global__ __launch_bounds__(256)
void k_scatter(const float* __restrict__ seg_points) {
    const int i = blockIdx.x * 256 + threadIdx.x;   // 0..4095
    const float x = __ldg(&seg_points[i * 3 + 0]);
    const float y = __ldg(&seg_points[i * 3 + 1]);
    const int pos = atomicAdd(&g_cursor[cell_of(x, y)], 1);
    g_sorted[pos] = make_float4(x, y, __int_as_float(i), 0.0f);
}

// ── Kernel 3: query (16 lanes per pillar) + fuse (warp per 2 pillars) ───
// 256 threads/block → 16 pillars/block → grid 1024
__global__ __launch_bounds__(256)
void k_query_fuse(const float* __restrict__ pillar_feature,
                  const int*   __restrict__ coors,
                  const float* __restrict__ seg_feats,
                  float*       __restrict__ out) {
    __shared__ int4 sidx[16];

    const int t    = threadIdx.x;
    const int warp = t >> 5;
    const int lane = t & 31;
    const int sub  = lane & 15;           // lane within group of 16
    const int pl   = t >> 4;              // pillar within block (0..15)
    const int m    = blockIdx.x * 16 + pl;

    // ── Phase A: 16-lane ball query ──
    {
        const int4 cr = __ldg((const int4*)coors + m);   // [0,0,y,x]
        const float px = ((float)cr.w + 0.5f) * VX;
        const float py = ((float)cr.z + 0.5f) * VY + PCY;

        const int cx = min(max((int)floorf(px), 0), GW - 1);
        const int cy = min(max((int)floorf(py + 25.6f), 0), GW - 1);
        const int cx0 = max(cx - 1, 0), cx1 = min(cx + 1, GW - 1);
        const int cy0 = max(cy - 1, 0), cy1 = min(cy + 1, GW - 1);
        const int cyn = cy1 - cy0;        // 1 or 2 extra rows

        // Hoist all row ranges: 6 independent loads (MLP)
        int s0, e0, s1, e1, s2, e2;
        s0 = __ldg(&g_bin_start[cy0 * GW + cx0]);
        e0 = __ldg(&g_bin_start[cy0 * GW + cx1 + 1]);
        {
            const int gy1 = min(cy0 + 1, cy1);
            s1 = __ldg(&g_bin_start[gy1 * GW + cx0]);
            e1 = __ldg(&g_bin_start[gy1 * GW + cx1 + 1]);
            const int gy2 = cy1;
            s2 = __ldg(&g_bin_start[gy2 * GW + cx0]);
            e2 = __ldg(&g_bin_start[gy2 * GW + cx1 + 1]);
        }
        if (cyn < 1) { s1 = 0; e1 = 0; }
        if (cyn < 2) { s2 = 0; e2 = 0; }

        // Concatenated range: one loop, usually 1 iteration per lane
        const int len0  = e0 - s0;
        const int len01 = len0 + (e1 - s1);
        const int total = len01 + (e2 - s2);

        // per-lane 4 smallest in-radius indices (sorted ascending)
        unsigned c0 = SENT, c1 = SENT, c2 = SENT, c3 = SENT;

        for (int l = sub; l < total; l += 16) {
            int j = (l < len0)  ? (s0 + l)
                  : (l < len01) ? (s1 + l - len0)
                                : (s2 + l - len01);
            float4 p = g_sorted[j];
            float dx = px - p.x;
            float dy = py - p.y;
            if (dx * dx + dy * dy < RADIUS2) {
                unsigned v = (unsigned)__float_as_int(p.z);
                if (v < c3) {
                    c3 = v;
                    unsigned tmp;
                    if (c3 < c2) { tmp = c2; c2 = c3; c3 = tmp; }
                    if (c2 < c1) { tmp = c1; c1 = c2; c2 = tmp; }
                    if (c1 < c0) { tmp = c0; c0 = c1; c1 = tmp; }
                }
            }
        }

        // 16-lane merge via REDUX: ALWAYS 4 rounds, no divergent exit.
        const unsigned gmask = 0xFFFFu << (lane & 16);
        unsigned res0, res1, res2, res3;
        {
            unsigned mn;
            #define QMIN(dst)                                                \
                mn = __reduce_min_sync(gmask, c0);                           \
                dst = mn;                                                    \
                if (c0 == mn && mn != SENT) { c0 = c1; c1 = c2; c2 = c3; c3 = SENT; }
            QMIN(res0)
            QMIN(res1)
            QMIN(res2)
            QMIN(res3)
            #undef QMIN
        }

        int i0, i1, i2, i3;
        if (res0 == SENT) { i0 = i1 = i2 = i3 = 0; }
        else {
            i0 = (int)res0;
            i1 = (res1 == SENT) ? i0 : (int)res1;
            i2 = (res2 == SENT) ? i0 : (int)res2;
            i3 = (res3 == SENT) ? i0 : (int)res3;
        }
        if (sub == 0) sidx[pl] = make_int4(i0, i1, i2, i3);
    }
    __syncthreads();

    // ── Phase B: warp-per-pillar coalesced fuse (2 pillars per warp) ──
    const int pbase = blockIdx.x * 16 + warp * 2;

    #pragma unroll
    for (int k = 0; k < 2; k++) {
        const int p = pbase + k;
        const int4 id = sidx[warp * 2 + k];

        const size_t mrow = (size_t)p * C_FEAT;
        float v0 = pillar_feature[mrow + lane];
        float v1 = pillar_feature[mrow + lane + 32];

        // Reference quirk: flag = (sum of indices) > 0
        if (id.x + id.y + id.z + id.w > 0) {
            const size_t r0 = (size_t)id.x * C_FEAT;
            const size_t r1 = (size_t)id.y * C_FEAT;
            const size_t r2 = (size_t)id.z * C_FEAT;
            const size_t r3 = (size_t)id.w * C_FEAT;

            float a0 = seg_feats[r0 + lane];
            float a1 = seg_feats[r1 + lane];
            float a2 = seg_feats[r2 + lane];
            float a3 = seg_feats[r3 + lane];
            float b0 = seg_feats[r0 + lane + 32];
            float b1 = seg_feats[r1 + lane + 32];
            float b2 = seg_feats[r2 + lane + 32];
            float b3 = seg_feats[r3 + lane + 32];

            v0 += fmaxf(fmaxf(a0, a1), fmaxf(a2, a3));
            v1 += fmaxf(fmaxf(b0, b1), fmaxf(b2, b3));
        }

        out[mrow + lane]      = v0;
        out[mrow + lane + 32] = v1;
    }
}

extern "C" void kernel_launch(void* const* d_in, const int* in_sizes, int n_in,
                              void* d_out, int out_size) {
    const float* pillar_feature = (const float*)d_in[0];  // [M, 64]
    const int*   coors          = (const int*)  d_in[1];  // [M, 4]
    const float* seg_feats      = (const float*)d_in[2];  // [N, 64]
    const float* seg_points     = (const float*)d_in[3];  // [N, 3]
    float* out = (float*)d_out;                            // [M, 64]

    k_count_scan<<<1, 1024>>>(seg_points);
    k_scatter<<<N_POINTS / 256, 256>>>(seg_points);
    k_query_fuse<<<M_PILLARS / 16, 256>>>(pillar_feature, coors, seg_feats, out);
}